// round 1
// baseline (speedup 1.0000x reference)
#include <cuda_runtime.h>
#include <math.h>

#define BATCH 16
#define SEQ   1024
#define DIM   768
#define NHEAD 12
#define HDIM  64
#define QK_SCALE 0.125f   // 64^-0.5

#define M_TOK (BATCH * SEQ)      // 16384
#define QKV_E (3 * DIM)          // 2304

// Scratch (allowed: __device__ globals, not runtime allocation)
__device__ float g_qkv[(size_t)M_TOK * QKV_E];  // [16384, 2304]
__device__ float g_ao [(size_t)M_TOK * DIM];    // [16384, 768]

// ---------------------------------------------------------------------------
// SGEMM (NT): C[M,Nn] = A[M,K] * B[Nn,K]^T (+ bias[Nn])
// Tiles: BM=128, BN=128, BK=16, 256 threads, 8x8 per thread.
// All dims here are exact multiples of the tiles (16384, 2304/768, 768).
// ---------------------------------------------------------------------------
__global__ __launch_bounds__(256) void sgemm_nt_kernel(
    const float* __restrict__ A,
    const float* __restrict__ Bm,
    const float* __restrict__ bias,
    float* __restrict__ C,
    int M, int Nn, int K)
{
    const int BM = 128, BN = 128, BK = 16;
    __shared__ float As[BK][BM];
    __shared__ float Bs[BK][BN];

    const int tid = threadIdx.x;
    const int ty = tid >> 4;       // 0..15
    const int tx = tid & 15;       // 0..15
    const int bx = blockIdx.x;     // N tile
    const int by = blockIdx.y;     // M tile

    const float* Ab = A  + (size_t)by * BM * K;
    const float* Bb = Bm + (size_t)bx * BN * K;

    const int lr = tid >> 2;        // 0..63
    const int lc = (tid & 3) * 4;   // 0,4,8,12

    float acc[8][8];
#pragma unroll
    for (int i = 0; i < 8; i++)
#pragma unroll
        for (int j = 0; j < 8; j++) acc[i][j] = 0.0f;

    for (int k0 = 0; k0 < K; k0 += BK) {
#pragma unroll
        for (int p = 0; p < 2; p++) {
            int row = lr + p * 64;
            float4 va = *(const float4*)(Ab + (size_t)row * K + k0 + lc);
            As[lc + 0][row] = va.x; As[lc + 1][row] = va.y;
            As[lc + 2][row] = va.z; As[lc + 3][row] = va.w;
            float4 vb = *(const float4*)(Bb + (size_t)row * K + k0 + lc);
            Bs[lc + 0][row] = vb.x; Bs[lc + 1][row] = vb.y;
            Bs[lc + 2][row] = vb.z; Bs[lc + 3][row] = vb.w;
        }
        __syncthreads();

#pragma unroll
        for (int kk = 0; kk < BK; kk++) {
            float a[8], b[8];
            float4 a0 = *(const float4*)&As[kk][ty * 8];
            float4 a1 = *(const float4*)&As[kk][ty * 8 + 4];
            a[0]=a0.x; a[1]=a0.y; a[2]=a0.z; a[3]=a0.w;
            a[4]=a1.x; a[5]=a1.y; a[6]=a1.z; a[7]=a1.w;
            float4 b0 = *(const float4*)&Bs[kk][tx * 8];
            float4 b1 = *(const float4*)&Bs[kk][tx * 8 + 4];
            b[0]=b0.x; b[1]=b0.y; b[2]=b0.z; b[3]=b0.w;
            b[4]=b1.x; b[5]=b1.y; b[6]=b1.z; b[7]=b1.w;
#pragma unroll
            for (int i = 0; i < 8; i++)
#pragma unroll
                for (int j = 0; j < 8; j++)
                    acc[i][j] = fmaf(a[i], b[j], acc[i][j]);
        }
        __syncthreads();
    }

    float bv[8];
#pragma unroll
    for (int j = 0; j < 8; j++)
        bv[j] = bias ? bias[bx * BN + tx * 8 + j] : 0.0f;

#pragma unroll
    for (int i = 0; i < 8; i++) {
        size_t m = (size_t)by * BM + ty * 8 + i;
        float* Crow = C + m * Nn + bx * BN + tx * 8;
#pragma unroll
        for (int j = 0; j < 8; j++)
            Crow[j] = acc[i][j] + bv[j];
    }
}

// ---------------------------------------------------------------------------
// Flash-style attention, fp32. One block = one (b, h, 64-query tile).
// Streams K/V tiles of 64 through smem, online softmax, P reuses K buffer.
// 256 threads: (ty,tx) in 16x16, each owns a 4x4 microtile of S / O.
// ---------------------------------------------------------------------------
#define APAD 68   // 64 + 4 pad (keeps 16B alignment, breaks row-stride conflicts)

__global__ __launch_bounds__(256) void attn_kernel(
    const float* __restrict__ qkv, float* __restrict__ ao)
{
    extern __shared__ float sm[];
    float* Qs = sm;                   // [64][APAD]
    float* Ks = sm + 64 * APAD;       // [64][APAD], reused for P
    float* Vs = sm + 2 * 64 * APAD;   // [64][APAD]

    const int qt = blockIdx.x;        // query tile 0..15
    const int bh = blockIdx.y;        // 0..191
    const int b = bh / NHEAD;
    const int h = bh % NHEAD;

    const int tid = threadIdx.x;
    const int ty = tid >> 4;          // 0..15
    const int tx = tid & 15;          // 0..15

    const size_t rs = QKV_E;          // row stride in qkv (2304)
    const float* Qg = qkv + ((size_t)(b * SEQ + qt * 64)) * rs + h * HDIM;
    const float* Kg = qkv + ((size_t)(b * SEQ)) * rs + (NHEAD + h) * HDIM;
    const float* Vg = qkv + ((size_t)(b * SEQ)) * rs + (2 * NHEAD + h) * HDIM;

    // Load Q tile (64x64) once
#pragma unroll
    for (int p = 0; p < 4; p++) {
        int idx = tid + p * 256;
        int r = idx >> 4;
        int c = (idx & 15) * 4;
        *(float4*)&Qs[r * APAD + c] = *(const float4*)(Qg + (size_t)r * rs + c);
    }

    float m_i[4], l_i[4], o[4][4];
#pragma unroll
    for (int i = 0; i < 4; i++) {
        m_i[i] = -INFINITY; l_i[i] = 0.0f;
#pragma unroll
        for (int j = 0; j < 4; j++) o[i][j] = 0.0f;
    }

    for (int jt = 0; jt < SEQ / 64; jt++) {
        __syncthreads();  // Q ready (iter 0); P/V consumed (iter > 0)
#pragma unroll
        for (int p = 0; p < 4; p++) {
            int idx = tid + p * 256;
            int r = idx >> 4;
            int c = (idx & 15) * 4;
            *(float4*)&Ks[r * APAD + c] =
                *(const float4*)(Kg + (size_t)(jt * 64 + r) * rs + c);
            *(float4*)&Vs[r * APAD + c] =
                *(const float4*)(Vg + (size_t)(jt * 64 + r) * rs + c);
        }
        __syncthreads();

        // S = Q * K^T  (rows 4*ty+i, cols 4*tx+j)
        float s[4][4];
#pragma unroll
        for (int i = 0; i < 4; i++)
#pragma unroll
            for (int j = 0; j < 4; j++) s[i][j] = 0.0f;

#pragma unroll 4
        for (int k = 0; k < 64; k++) {
            float q[4], kv[4];
#pragma unroll
            for (int i = 0; i < 4; i++) q[i]  = Qs[(ty * 4 + i) * APAD + k];
#pragma unroll
            for (int j = 0; j < 4; j++) kv[j] = Ks[(tx * 4 + j) * APAD + k];
#pragma unroll
            for (int i = 0; i < 4; i++)
#pragma unroll
                for (int j = 0; j < 4; j++)
                    s[i][j] = fmaf(q[i], kv[j], s[i][j]);
        }

        // Online softmax per row (reduce across the 16 tx lanes)
#pragma unroll
        for (int i = 0; i < 4; i++) {
            float mx = -INFINITY;
#pragma unroll
            for (int j = 0; j < 4; j++) {
                s[i][j] *= QK_SCALE;
                mx = fmaxf(mx, s[i][j]);
            }
#pragma unroll
            for (int off = 8; off >= 1; off >>= 1)
                mx = fmaxf(mx, __shfl_xor_sync(0xffffffffu, mx, off));

            float mnew = fmaxf(m_i[i], mx);
            float alpha = __expf(m_i[i] - mnew);
            m_i[i] = mnew;

            float rsum = 0.0f;
#pragma unroll
            for (int j = 0; j < 4; j++) {
                float p = __expf(s[i][j] - mnew);
                s[i][j] = p;
                rsum += p;
            }
#pragma unroll
            for (int off = 8; off >= 1; off >>= 1)
                rsum += __shfl_xor_sync(0xffffffffu, rsum, off);

            l_i[i] = l_i[i] * alpha + rsum;
#pragma unroll
            for (int j = 0; j < 4; j++) o[i][j] *= alpha;
        }

        __syncthreads();  // everyone done reading Ks as K
        // Write P into the K buffer
#pragma unroll
        for (int i = 0; i < 4; i++)
#pragma unroll
            for (int j = 0; j < 4; j++)
                Ks[(ty * 4 + i) * APAD + tx * 4 + j] = s[i][j];
        __syncthreads();

        // O += P * V (O cols = head dim 4*tx+j)
#pragma unroll 4
        for (int k = 0; k < 64; k++) {
            float pk[4], vv[4];
#pragma unroll
            for (int i = 0; i < 4; i++) pk[i] = Ks[(ty * 4 + i) * APAD + k];
#pragma unroll
            for (int j = 0; j < 4; j++) vv[j] = Vs[k * APAD + tx * 4 + j];
#pragma unroll
            for (int i = 0; i < 4; i++)
#pragma unroll
                for (int j = 0; j < 4; j++)
                    o[i][j] = fmaf(pk[i], vv[j], o[i][j]);
        }
    }

    // Epilogue: normalize and write to [b, n, h*HDIM + d] layout (row-major 768)
#pragma unroll
    for (int i = 0; i < 4; i++) {
        float inv = 1.0f / l_i[i];
        size_t n_tok = (size_t)b * SEQ + qt * 64 + ty * 4 + i;
        float* dst = ao + n_tok * DIM + h * HDIM + tx * 4;
#pragma unroll
        for (int j = 0; j < 4; j++)
            dst[j] = o[i][j] * inv;
    }
}

// ---------------------------------------------------------------------------
extern "C" void kernel_launch(void* const* d_in, const int* in_sizes, int n_in,
                              void* d_out, int out_size)
{
    const float* x      = (const float*)d_in[0];   // [16,1024,768]
    const float* w_qkv  = (const float*)d_in[1];   // [2304,768]
    const float* w_proj = (const float*)d_in[2];   // [768,768]
    const float* b_proj = (const float*)d_in[3];   // [768]
    float* out = (float*)d_out;                    // [16,1024,768]

    float* qkv = nullptr;
    float* ao  = nullptr;
    cudaGetSymbolAddress((void**)&qkv, g_qkv);
    cudaGetSymbolAddress((void**)&ao,  g_ao);

    // 1) QKV projection: [16384,2304] = x[16384,768] * w_qkv^T
    dim3 g1(QKV_E / 128, M_TOK / 128);   // (18, 128)
    sgemm_nt_kernel<<<g1, 256>>>(x, w_qkv, nullptr, qkv, M_TOK, QKV_E, DIM);

    // 2) Attention
    const int smem_bytes = 3 * 64 * APAD * (int)sizeof(float);  // 52224
    cudaFuncSetAttribute(attn_kernel,
                         cudaFuncAttributeMaxDynamicSharedMemorySize, smem_bytes);
    dim3 g2(SEQ / 64, BATCH * NHEAD);    // (16, 192)
    attn_kernel<<<g2, 256, smem_bytes>>>(qkv, ao);

    // 3) Output projection: out = ao * w_proj^T + b_proj
    dim3 g3(DIM / 128, M_TOK / 128);     // (6, 128)
    sgemm_nt_kernel<<<g3, 256>>>(ao, w_proj, b_proj, out, M_TOK, DIM, DIM);
}

// round 3
// speedup vs baseline: 1.3697x; 1.3697x over previous
#include <cuda_runtime.h>
#include <cuda_bf16.h>
#include <math.h>
#include <stdint.h>

#define BATCH 16
#define SEQ   1024
#define DIM   768
#define NHEAD 12
#define HDIM  64
#define QK_SCALE 0.125f   // 64^-0.5

#define M_TOK (BATCH * SEQ)      // 16384
#define QKV_E (3 * DIM)          // 2304

// Scratch (allowed: __device__ globals)
__device__ float g_qkv[(size_t)M_TOK * QKV_E];  // [16384, 2304]
__device__ float g_ao [(size_t)M_TOK * DIM];    // [16384, 768]

__device__ __forceinline__ uint32_t smem_u32(const void* p) {
    uint32_t a;
    asm("{ .reg .u64 t; cvta.to.shared.u64 t, %1; cvt.u32.u64 %0, t; }"
        : "=r"(a) : "l"(p));
    return a;
}

__device__ __forceinline__ void ldm_x4(uint32_t& r0, uint32_t& r1,
                                       uint32_t& r2, uint32_t& r3,
                                       uint32_t addr) {
    asm volatile("ldmatrix.sync.aligned.m8n8.x4.shared.b16 {%0,%1,%2,%3}, [%4];"
                 : "=r"(r0), "=r"(r1), "=r"(r2), "=r"(r3) : "r"(addr));
}

__device__ __forceinline__ void mma_bf16(float* c, const uint32_t* a,
                                         const uint32_t* b) {
    asm volatile(
        "mma.sync.aligned.m16n8k16.row.col.f32.bf16.bf16.f32 "
        "{%0,%1,%2,%3}, {%4,%5,%6,%7}, {%8,%9}, {%0,%1,%2,%3};"
        : "+f"(c[0]), "+f"(c[1]), "+f"(c[2]), "+f"(c[3])
        : "r"(a[0]), "r"(a[1]), "r"(a[2]), "r"(a[3]), "r"(b[0]), "r"(b[1]));
}

// ---------------------------------------------------------------------------
// Split-bf16 HMMA GEMM (NT): C[M,Nn] = A[M,K]*B[Nn,K]^T (+bias)
// CTA 128x128, BK=32, 256 thr (8 warps, warp tile 64x32), 3-term bf16 split.
// smem rows padded to 80 B (40 bf16) -> conflict-free ldmatrix.
// ---------------------------------------------------------------------------
#define SROWB 80                     // bytes per smem row
#define TILEB (128 * SROWB)          // 10240 B per tile
#define STAGEB (4 * TILEB)           // Ahi,Alo,Bhi,Blo = 40960 B
#define SMEM_GEMM (2 * STAGEB)       // 81920 B

__global__ __launch_bounds__(256, 1) void gemm_mma_kernel(
    const float* __restrict__ A,
    const float* __restrict__ Bm,
    const float* __restrict__ bias,
    float* __restrict__ C,
    int Nn, int K)
{
    extern __shared__ __align__(128) char smc[];
    const uint32_t sb = smem_u32(smc);

    const int tid = threadIdx.x;
    const int lane = tid & 31;
    const int wid = tid >> 5;
    const int wm = wid >> 2;          // 0..1  (64-row slab)
    const int wn = wid & 3;           // 0..3  (32-col slab)
    const int bx = blockIdx.x;
    const int by = blockIdx.y;

    const float* Ab = A  + (size_t)by * 128 * K;
    const float* Bb = Bm + (size_t)bx * 128 * K;

    // staging decomposition: 128x32 fp32 per tile -> 4 float4 per thread
    const int srow0 = tid >> 3;       // 0..31, + 32*p
    const int scol  = (tid & 7) * 4;  // element col 0..28

    // ldmatrix per-lane base offsets (bytes within a tile)
    const uint32_t a_lm = (uint32_t)((lane & 15) * SROWB + (lane >> 4) * 16)
                        + (uint32_t)(wm * 64 * SROWB);
    const uint32_t b_lm = (uint32_t)((((lane >> 4) << 3) + (lane & 7)) * SROWB
                        + ((lane >> 3) & 1) * 16)
                        + (uint32_t)(wn * 32 * SROWB);

    float c[4][4][4];
#pragma unroll
    for (int i = 0; i < 4; i++)
#pragma unroll
        for (int j = 0; j < 4; j++)
#pragma unroll
            for (int q = 0; q < 4; q++) c[i][j][q] = 0.0f;

    const int NC = K / 32;
    float4 stA[4], stB[4];

    // ---- prologue: load + convert + store chunk 0 into stage 0 ----
#pragma unroll
    for (int p = 0; p < 4; p++) {
        int r = srow0 + 32 * p;
        stA[p] = *(const float4*)(Ab + (size_t)r * K + scol);
        stB[p] = *(const float4*)(Bb + (size_t)r * K + scol);
    }
    {
        char* Ahi = smc;
        char* Alo = smc + TILEB;
        char* Bhi = smc + 2 * TILEB;
        char* Blo = smc + 3 * TILEB;
#pragma unroll
        for (int p = 0; p < 4; p++) {
            int r = srow0 + 32 * p;
            uint32_t off = (uint32_t)(r * SROWB + scol * 2);
            float4 v = stA[p];
            __nv_bfloat162 h0 = __floats2bfloat162_rn(v.x, v.y);
            __nv_bfloat162 h1 = __floats2bfloat162_rn(v.z, v.w);
            __nv_bfloat162 l0 = __floats2bfloat162_rn(
                v.x - __bfloat162float(__low2bfloat16(h0)),
                v.y - __bfloat162float(__high2bfloat16(h0)));
            __nv_bfloat162 l1 = __floats2bfloat162_rn(
                v.z - __bfloat162float(__low2bfloat16(h1)),
                v.w - __bfloat162float(__high2bfloat16(h1)));
            *(uint2*)(Ahi + off) = make_uint2(*(uint32_t*)&h0, *(uint32_t*)&h1);
            *(uint2*)(Alo + off) = make_uint2(*(uint32_t*)&l0, *(uint32_t*)&l1);
            v = stB[p];
            h0 = __floats2bfloat162_rn(v.x, v.y);
            h1 = __floats2bfloat162_rn(v.z, v.w);
            l0 = __floats2bfloat162_rn(
                v.x - __bfloat162float(__low2bfloat16(h0)),
                v.y - __bfloat162float(__high2bfloat16(h0)));
            l1 = __floats2bfloat162_rn(
                v.z - __bfloat162float(__low2bfloat16(h1)),
                v.w - __bfloat162float(__high2bfloat16(h1)));
            *(uint2*)(Bhi + off) = make_uint2(*(uint32_t*)&h0, *(uint32_t*)&h1);
            *(uint2*)(Blo + off) = make_uint2(*(uint32_t*)&l0, *(uint32_t*)&l1);
        }
    }

    for (int ic = 0; ic < NC; ic++) {
        __syncthreads();

        // issue next chunk's global loads early (hidden under the MMAs)
        const bool more = (ic + 1) < NC;
        if (more) {
            const int k0 = (ic + 1) * 32;
#pragma unroll
            for (int p = 0; p < 4; p++) {
                int r = srow0 + 32 * p;
                stA[p] = *(const float4*)(Ab + (size_t)r * K + k0 + scol);
                stB[p] = *(const float4*)(Bb + (size_t)r * K + k0 + scol);
            }
        }

        // ---- MMA on current stage ----
        const uint32_t su = sb + (uint32_t)((ic & 1) * STAGEB);
#pragma unroll
        for (int ks = 0; ks < 2; ks++) {
            const uint32_t kofs = (uint32_t)(ks * 32);  // 16 bf16 = 32 B
            uint32_t ah[4][4], al[4][4], bh[4][2], bl[4][2];
#pragma unroll
            for (int im = 0; im < 4; im++) {
                uint32_t base = su + a_lm + (uint32_t)(im * 16 * SROWB) + kofs;
                ldm_x4(ah[im][0], ah[im][1], ah[im][2], ah[im][3], base);
                ldm_x4(al[im][0], al[im][1], al[im][2], al[im][3], base + TILEB);
            }
#pragma unroll
            for (int in2 = 0; in2 < 2; in2++) {
                uint32_t base = su + 2 * TILEB + b_lm
                              + (uint32_t)(in2 * 16 * SROWB) + kofs;
                uint32_t r0, r1, r2, r3;
                ldm_x4(r0, r1, r2, r3, base);
                bh[in2 * 2][0] = r0; bh[in2 * 2][1] = r1;
                bh[in2 * 2 + 1][0] = r2; bh[in2 * 2 + 1][1] = r3;
                ldm_x4(r0, r1, r2, r3, base + TILEB);
                bl[in2 * 2][0] = r0; bl[in2 * 2][1] = r1;
                bl[in2 * 2 + 1][0] = r2; bl[in2 * 2 + 1][1] = r3;
            }
#pragma unroll
            for (int im = 0; im < 4; im++)
#pragma unroll
                for (int inn = 0; inn < 4; inn++) {
                    mma_bf16(c[im][inn], ah[im], bh[inn]);
                    mma_bf16(c[im][inn], ah[im], bl[inn]);
                    mma_bf16(c[im][inn], al[im], bh[inn]);
                }
        }

        // ---- convert + store next chunk into the other stage ----
        if (more) {
            char* base = smc + ((ic + 1) & 1) * STAGEB;
            char* Ahi = base;
            char* Alo = base + TILEB;
            char* Bhi = base + 2 * TILEB;
            char* Blo = base + 3 * TILEB;
#pragma unroll
            for (int p = 0; p < 4; p++) {
                int r = srow0 + 32 * p;
                uint32_t off = (uint32_t)(r * SROWB + scol * 2);
                float4 v = stA[p];
                __nv_bfloat162 h0 = __floats2bfloat162_rn(v.x, v.y);
                __nv_bfloat162 h1 = __floats2bfloat162_rn(v.z, v.w);
                __nv_bfloat162 l0 = __floats2bfloat162_rn(
                    v.x - __bfloat162float(__low2bfloat16(h0)),
                    v.y - __bfloat162float(__high2bfloat16(h0)));
                __nv_bfloat162 l1 = __floats2bfloat162_rn(
                    v.z - __bfloat162float(__low2bfloat16(h1)),
                    v.w - __bfloat162float(__high2bfloat16(h1)));
                *(uint2*)(Ahi + off) = make_uint2(*(uint32_t*)&h0, *(uint32_t*)&h1);
                *(uint2*)(Alo + off) = make_uint2(*(uint32_t*)&l0, *(uint32_t*)&l1);
                v = stB[p];
                h0 = __floats2bfloat162_rn(v.x, v.y);
                h1 = __floats2bfloat162_rn(v.z, v.w);
                l0 = __floats2bfloat162_rn(
                    v.x - __bfloat162float(__low2bfloat16(h0)),
                    v.y - __bfloat162float(__high2bfloat16(h0)));
                l1 = __floats2bfloat162_rn(
                    v.z - __bfloat162float(__low2bfloat16(h1)),
                    v.w - __bfloat162float(__high2bfloat16(h1)));
                *(uint2*)(Bhi + off) = make_uint2(*(uint32_t*)&h0, *(uint32_t*)&h1);
                *(uint2*)(Blo + off) = make_uint2(*(uint32_t*)&l0, *(uint32_t*)&l1);
            }
        }
    }

    // ---- epilogue ----
#pragma unroll
    for (int im = 0; im < 4; im++) {
        const size_t row = (size_t)by * 128 + wm * 64 + im * 16 + (lane >> 2);
#pragma unroll
        for (int inn = 0; inn < 4; inn++) {
            const int col = bx * 128 + wn * 32 + inn * 8 + (lane & 3) * 2;
            float b0 = 0.0f, b1 = 0.0f;
            if (bias) { b0 = bias[col]; b1 = bias[col + 1]; }
            float2 v0 = make_float2(c[im][inn][0] + b0, c[im][inn][1] + b1);
            float2 v1 = make_float2(c[im][inn][2] + b0, c[im][inn][3] + b1);
            *(float2*)(C + row * Nn + col) = v0;
            *(float2*)(C + (row + 8) * Nn + col) = v1;
        }
    }
}

// ===========================================================================
// Flash-style attention, fp32 (unchanged — round 4 target)
// ===========================================================================
#define APAD 68

__global__ __launch_bounds__(256) void attn_kernel(
    const float* __restrict__ qkv, float* __restrict__ ao)
{
    extern __shared__ float sm[];
    float* Qs = sm;
    float* Ks = sm + 64 * APAD;
    float* Vs = sm + 2 * 64 * APAD;

    const int qt = blockIdx.x;
    const int bh = blockIdx.y;
    const int b = bh / NHEAD;
    const int h = bh % NHEAD;

    const int tid = threadIdx.x;
    const int ty = tid >> 4;
    const int tx = tid & 15;

    const size_t rs = QKV_E;
    const float* Qg = qkv + ((size_t)(b * SEQ + qt * 64)) * rs + h * HDIM;
    const float* Kg = qkv + ((size_t)(b * SEQ)) * rs + (NHEAD + h) * HDIM;
    const float* Vg = qkv + ((size_t)(b * SEQ)) * rs + (2 * NHEAD + h) * HDIM;

#pragma unroll
    for (int p = 0; p < 4; p++) {
        int idx = tid + p * 256;
        int r = idx >> 4;
        int cc = (idx & 15) * 4;
        *(float4*)&Qs[r * APAD + cc] = *(const float4*)(Qg + (size_t)r * rs + cc);
    }

    float m_i[4], l_i[4], o[4][4];
#pragma unroll
    for (int i = 0; i < 4; i++) {
        m_i[i] = -INFINITY; l_i[i] = 0.0f;
#pragma unroll
        for (int j = 0; j < 4; j++) o[i][j] = 0.0f;
    }

    for (int jt = 0; jt < SEQ / 64; jt++) {
        __syncthreads();
#pragma unroll
        for (int p = 0; p < 4; p++) {
            int idx = tid + p * 256;
            int r = idx >> 4;
            int cc = (idx & 15) * 4;
            *(float4*)&Ks[r * APAD + cc] =
                *(const float4*)(Kg + (size_t)(jt * 64 + r) * rs + cc);
            *(float4*)&Vs[r * APAD + cc] =
                *(const float4*)(Vg + (size_t)(jt * 64 + r) * rs + cc);
        }
        __syncthreads();

        float s[4][4];
#pragma unroll
        for (int i = 0; i < 4; i++)
#pragma unroll
            for (int j = 0; j < 4; j++) s[i][j] = 0.0f;

#pragma unroll 4
        for (int k = 0; k < 64; k++) {
            float q[4], kv[4];
#pragma unroll
            for (int i = 0; i < 4; i++) q[i]  = Qs[(ty * 4 + i) * APAD + k];
#pragma unroll
            for (int j = 0; j < 4; j++) kv[j] = Ks[(tx * 4 + j) * APAD + k];
#pragma unroll
            for (int i = 0; i < 4; i++)
#pragma unroll
                for (int j = 0; j < 4; j++)
                    s[i][j] = fmaf(q[i], kv[j], s[i][j]);
        }

#pragma unroll
        for (int i = 0; i < 4; i++) {
            float mx = -INFINITY;
#pragma unroll
            for (int j = 0; j < 4; j++) {
                s[i][j] *= QK_SCALE;
                mx = fmaxf(mx, s[i][j]);
            }
#pragma unroll
            for (int off = 8; off >= 1; off >>= 1)
                mx = fmaxf(mx, __shfl_xor_sync(0xffffffffu, mx, off));

            float mnew = fmaxf(m_i[i], mx);
            float alpha = __expf(m_i[i] - mnew);
            m_i[i] = mnew;

            float rsum = 0.0f;
#pragma unroll
            for (int j = 0; j < 4; j++) {
                float p = __expf(s[i][j] - mnew);
                s[i][j] = p;
                rsum += p;
            }
#pragma unroll
            for (int off = 8; off >= 1; off >>= 1)
                rsum += __shfl_xor_sync(0xffffffffu, rsum, off);

            l_i[i] = l_i[i] * alpha + rsum;
#pragma unroll
            for (int j = 0; j < 4; j++) o[i][j] *= alpha;
        }

        __syncthreads();
#pragma unroll
        for (int i = 0; i < 4; i++)
#pragma unroll
            for (int j = 0; j < 4; j++)
                Ks[(ty * 4 + i) * APAD + tx * 4 + j] = s[i][j];
        __syncthreads();

#pragma unroll 4
        for (int k = 0; k < 64; k++) {
            float pk[4], vv[4];
#pragma unroll
            for (int i = 0; i < 4; i++) pk[i] = Ks[(ty * 4 + i) * APAD + k];
#pragma unroll
            for (int j = 0; j < 4; j++) vv[j] = Vs[k * APAD + tx * 4 + j];
#pragma unroll
            for (int i = 0; i < 4; i++)
#pragma unroll
                for (int j = 0; j < 4; j++)
                    o[i][j] = fmaf(pk[i], vv[j], o[i][j]);
        }
    }

#pragma unroll
    for (int i = 0; i < 4; i++) {
        float inv = 1.0f / l_i[i];
        size_t n_tok = (size_t)b * SEQ + qt * 64 + ty * 4 + i;
        float* dst = ao + n_tok * DIM + h * HDIM + tx * 4;
#pragma unroll
        for (int j = 0; j < 4; j++)
            dst[j] = o[i][j] * inv;
    }
}

// ===========================================================================
extern "C" void kernel_launch(void* const* d_in, const int* in_sizes, int n_in,
                              void* d_out, int out_size)
{
    const float* x      = (const float*)d_in[0];   // [16,1024,768]
    const float* w_qkv  = (const float*)d_in[1];   // [2304,768]
    const float* w_proj = (const float*)d_in[2];   // [768,768]
    const float* b_proj = (const float*)d_in[3];   // [768]
    float* out = (float*)d_out;

    float* qkv = nullptr;
    float* ao  = nullptr;
    cudaGetSymbolAddress((void**)&qkv, g_qkv);
    cudaGetSymbolAddress((void**)&ao,  g_ao);

    cudaFuncSetAttribute(gemm_mma_kernel,
                         cudaFuncAttributeMaxDynamicSharedMemorySize, SMEM_GEMM);

    // 1) QKV projection (HMMA split-bf16)
    dim3 g1(QKV_E / 128, M_TOK / 128);   // (18, 128)
    gemm_mma_kernel<<<g1, 256, SMEM_GEMM>>>(x, w_qkv, nullptr, qkv, QKV_E, DIM);

    // 2) Attention (fp32 flash)
    const int smem_attn = 3 * 64 * APAD * (int)sizeof(float);
    cudaFuncSetAttribute(attn_kernel,
                         cudaFuncAttributeMaxDynamicSharedMemorySize, smem_attn);
    dim3 g2(SEQ / 64, BATCH * NHEAD);
    attn_kernel<<<g2, 256, smem_attn>>>(qkv, ao);

    // 3) Output projection (HMMA split-bf16, +bias)
    dim3 g3(DIM / 128, M_TOK / 128);     // (6, 128)
    gemm_mma_kernel<<<g3, 256, SMEM_GEMM>>>(ao, w_proj, b_proj, out, DIM, DIM);
}

// round 4
// speedup vs baseline: 3.7491x; 2.7372x over previous
#include <cuda_runtime.h>
#include <cuda_bf16.h>
#include <math.h>
#include <stdint.h>

#define BATCH 16
#define SEQ   1024
#define DIM   768
#define NHEAD 12
#define HDIM  64

#define M_TOK (BATCH * SEQ)      // 16384
#define QKV_E (3 * DIM)          // 2304

__device__ float g_qkv[(size_t)M_TOK * QKV_E];
__device__ float g_ao [(size_t)M_TOK * DIM];

__device__ __forceinline__ uint32_t smem_u32(const void* p) {
    uint32_t a;
    asm("{ .reg .u64 t; cvta.to.shared.u64 t, %1; cvt.u32.u64 %0, t; }"
        : "=r"(a) : "l"(p));
    return a;
}

__device__ __forceinline__ void ldm_x4(uint32_t& r0, uint32_t& r1,
                                       uint32_t& r2, uint32_t& r3,
                                       uint32_t addr) {
    asm volatile("ldmatrix.sync.aligned.m8n8.x4.shared.b16 {%0,%1,%2,%3}, [%4];"
                 : "=r"(r0), "=r"(r1), "=r"(r2), "=r"(r3) : "r"(addr));
}

__device__ __forceinline__ void mma_bf16(float* c, const uint32_t* a,
                                         const uint32_t* b) {
    asm volatile(
        "mma.sync.aligned.m16n8k16.row.col.f32.bf16.bf16.f32 "
        "{%0,%1,%2,%3}, {%4,%5,%6,%7}, {%8,%9}, {%0,%1,%2,%3};"
        : "+f"(c[0]), "+f"(c[1]), "+f"(c[2]), "+f"(c[3])
        : "r"(a[0]), "r"(a[1]), "r"(a[2]), "r"(a[3]), "r"(b[0]), "r"(b[1]));
}

__device__ __forceinline__ void split2(float x, float y,
                                       uint32_t& hi, uint32_t& lo) {
    __nv_bfloat162 h = __floats2bfloat162_rn(x, y);
    __nv_bfloat162 l = __floats2bfloat162_rn(
        x - __bfloat162float(__low2bfloat16(h)),
        y - __bfloat162float(__high2bfloat16(h)));
    hi = *(uint32_t*)&h;
    lo = *(uint32_t*)&l;
}

// ===========================================================================
// Split-bf16 HMMA GEMM (unchanged from round 3 — passed)
// ===========================================================================
#define SROWB 80
#define TILEB (128 * SROWB)
#define STAGEB (4 * TILEB)
#define SMEM_GEMM (2 * STAGEB)

__global__ __launch_bounds__(256, 1) void gemm_mma_kernel(
    const float* __restrict__ A,
    const float* __restrict__ Bm,
    const float* __restrict__ bias,
    float* __restrict__ C,
    int Nn, int K)
{
    extern __shared__ __align__(128) char smc[];
    const uint32_t sb = smem_u32(smc);

    const int tid = threadIdx.x;
    const int lane = tid & 31;
    const int wid = tid >> 5;
    const int wm = wid >> 2;
    const int wn = wid & 3;
    const int bx = blockIdx.x;
    const int by = blockIdx.y;

    const float* Ab = A  + (size_t)by * 128 * K;
    const float* Bb = Bm + (size_t)bx * 128 * K;

    const int srow0 = tid >> 3;
    const int scol  = (tid & 7) * 4;

    const uint32_t a_lm = (uint32_t)((lane & 15) * SROWB + (lane >> 4) * 16)
                        + (uint32_t)(wm * 64 * SROWB);
    const uint32_t b_lm = (uint32_t)((((lane >> 4) << 3) + (lane & 7)) * SROWB
                        + ((lane >> 3) & 1) * 16)
                        + (uint32_t)(wn * 32 * SROWB);

    float c[4][4][4];
#pragma unroll
    for (int i = 0; i < 4; i++)
#pragma unroll
        for (int j = 0; j < 4; j++)
#pragma unroll
            for (int q = 0; q < 4; q++) c[i][j][q] = 0.0f;

    const int NC = K / 32;
    float4 stA[4], stB[4];

#pragma unroll
    for (int p = 0; p < 4; p++) {
        int r = srow0 + 32 * p;
        stA[p] = *(const float4*)(Ab + (size_t)r * K + scol);
        stB[p] = *(const float4*)(Bb + (size_t)r * K + scol);
    }
    {
        char* Ahi = smc;
        char* Alo = smc + TILEB;
        char* Bhi = smc + 2 * TILEB;
        char* Blo = smc + 3 * TILEB;
#pragma unroll
        for (int p = 0; p < 4; p++) {
            int r = srow0 + 32 * p;
            uint32_t off = (uint32_t)(r * SROWB + scol * 2);
            uint32_t h0, h1, l0, l1;
            split2(stA[p].x, stA[p].y, h0, l0);
            split2(stA[p].z, stA[p].w, h1, l1);
            *(uint2*)(Ahi + off) = make_uint2(h0, h1);
            *(uint2*)(Alo + off) = make_uint2(l0, l1);
            split2(stB[p].x, stB[p].y, h0, l0);
            split2(stB[p].z, stB[p].w, h1, l1);
            *(uint2*)(Bhi + off) = make_uint2(h0, h1);
            *(uint2*)(Blo + off) = make_uint2(l0, l1);
        }
    }

    for (int ic = 0; ic < NC; ic++) {
        __syncthreads();

        const bool more = (ic + 1) < NC;
        if (more) {
            const int k0 = (ic + 1) * 32;
#pragma unroll
            for (int p = 0; p < 4; p++) {
                int r = srow0 + 32 * p;
                stA[p] = *(const float4*)(Ab + (size_t)r * K + k0 + scol);
                stB[p] = *(const float4*)(Bb + (size_t)r * K + k0 + scol);
            }
        }

        const uint32_t su = sb + (uint32_t)((ic & 1) * STAGEB);
#pragma unroll
        for (int ks = 0; ks < 2; ks++) {
            const uint32_t kofs = (uint32_t)(ks * 32);
            uint32_t ah[4][4], al[4][4], bh[4][2], bl[4][2];
#pragma unroll
            for (int im = 0; im < 4; im++) {
                uint32_t base = su + a_lm + (uint32_t)(im * 16 * SROWB) + kofs;
                ldm_x4(ah[im][0], ah[im][1], ah[im][2], ah[im][3], base);
                ldm_x4(al[im][0], al[im][1], al[im][2], al[im][3], base + TILEB);
            }
#pragma unroll
            for (int in2 = 0; in2 < 2; in2++) {
                uint32_t base = su + 2 * TILEB + b_lm
                              + (uint32_t)(in2 * 16 * SROWB) + kofs;
                uint32_t r0, r1, r2, r3;
                ldm_x4(r0, r1, r2, r3, base);
                bh[in2 * 2][0] = r0; bh[in2 * 2][1] = r1;
                bh[in2 * 2 + 1][0] = r2; bh[in2 * 2 + 1][1] = r3;
                ldm_x4(r0, r1, r2, r3, base + TILEB);
                bl[in2 * 2][0] = r0; bl[in2 * 2][1] = r1;
                bl[in2 * 2 + 1][0] = r2; bl[in2 * 2 + 1][1] = r3;
            }
#pragma unroll
            for (int im = 0; im < 4; im++)
#pragma unroll
                for (int inn = 0; inn < 4; inn++) {
                    mma_bf16(c[im][inn], ah[im], bh[inn]);
                    mma_bf16(c[im][inn], ah[im], bl[inn]);
                    mma_bf16(c[im][inn], al[im], bh[inn]);
                }
        }

        if (more) {
            char* base = smc + ((ic + 1) & 1) * STAGEB;
            char* Ahi = base;
            char* Alo = base + TILEB;
            char* Bhi = base + 2 * TILEB;
            char* Blo = base + 3 * TILEB;
#pragma unroll
            for (int p = 0; p < 4; p++) {
                int r = srow0 + 32 * p;
                uint32_t off = (uint32_t)(r * SROWB + scol * 2);
                uint32_t h0, h1, l0, l1;
                split2(stA[p].x, stA[p].y, h0, l0);
                split2(stA[p].z, stA[p].w, h1, l1);
                *(uint2*)(Ahi + off) = make_uint2(h0, h1);
                *(uint2*)(Alo + off) = make_uint2(l0, l1);
                split2(stB[p].x, stB[p].y, h0, l0);
                split2(stB[p].z, stB[p].w, h1, l1);
                *(uint2*)(Bhi + off) = make_uint2(h0, h1);
                *(uint2*)(Blo + off) = make_uint2(l0, l1);
            }
        }
    }

#pragma unroll
    for (int im = 0; im < 4; im++) {
        const size_t row = (size_t)by * 128 + wm * 64 + im * 16 + (lane >> 2);
#pragma unroll
        for (int inn = 0; inn < 4; inn++) {
            const int col = bx * 128 + wn * 32 + inn * 8 + (lane & 3) * 2;
            float b0 = 0.0f, b1 = 0.0f;
            if (bias) { b0 = bias[col]; b1 = bias[col + 1]; }
            float2 v0 = make_float2(c[im][inn][0] + b0, c[im][inn][1] + b1);
            float2 v1 = make_float2(c[im][inn][2] + b0, c[im][inn][3] + b1);
            *(float2*)(C + row * Nn + col) = v0;
            *(float2*)(C + (row + 8) * Nn + col) = v1;
        }
    }
}

// ===========================================================================
// Flash attention with split-bf16 HMMA.
// CTA = (128 queries) x (one b,h). 8 warps, 16 query rows each. Key tile 64.
// ===========================================================================
#define ASROW 144                          // 128B data + 16B pad per 64-elem row
#define AQHI  0
#define AQLO  (128 * ASROW)                // 18432
#define AKHI  (2 * 128 * ASROW)            // 36864
#define AKLO  (AKHI + 64 * ASROW)          // 46080
#define AVHI  (AKLO + 64 * ASROW)          // 55296
#define AVLO  (AVHI + 64 * ASROW)          // 64512
#define ASMEM (AVLO + 64 * ASROW)          // 73728

__global__ __launch_bounds__(256, 1) void attn_mma_kernel(
    const float* __restrict__ qkv, float* __restrict__ ao)
{
    extern __shared__ __align__(128) char smc[];
    const uint32_t sb = smem_u32(smc);

    const int tid = threadIdx.x;
    const int lane = tid & 31;
    const int wid = tid >> 5;

    const int qt = blockIdx.x;        // 0..7 (128-query tiles)
    const int bh = blockIdx.y;        // 0..191
    const int b = bh / NHEAD;
    const int h = bh % NHEAD;

    const size_t rs = QKV_E;
    const float* Qg = qkv + ((size_t)(b * SEQ + qt * 128)) * rs + h * HDIM;
    const float* Kg = qkv + ((size_t)(b * SEQ)) * rs + (NHEAD + h) * HDIM;
    const float* Vg = qkv + ((size_t)(b * SEQ)) * rs + (2 * NHEAD + h) * HDIM;

    // --- load Q (scaled by 2^-3), split into Qhi/Qlo ---
    {
        const int row = tid >> 1;
        const int cb = (tid & 1) * 4;          // float col base within 8-stride
        const float* src = Qg + (size_t)row * rs;
#pragma unroll
        for (int i = 0; i < 8; i++) {
            int cf = cb + i * 8;
            float4 v = *(const float4*)(src + cf);
            v.x *= 0.125f; v.y *= 0.125f; v.z *= 0.125f; v.w *= 0.125f;
            uint32_t h0, h1, l0, l1;
            split2(v.x, v.y, h0, l0);
            split2(v.z, v.w, h1, l1);
            uint32_t off = (uint32_t)(row * ASROW + cf * 2);
            *(uint2*)(smc + AQHI + off) = make_uint2(h0, h1);
            *(uint2*)(smc + AQLO + off) = make_uint2(l0, l1);
        }
    }

    // ldmatrix lane offsets
    const uint32_t a_lm = (uint32_t)((lane & 15) * ASROW + (lane >> 4) * 16);
    const uint32_t b_lm = (uint32_t)((((lane >> 4) << 3) + (lane & 7)) * ASROW
                        + ((lane >> 3) & 1) * 16);

    // K/V staging (thread: row tid>>2, 4 float4 at cols (tid&3)*4 + 16i)
    const int krow = tid >> 2;
    const int kcb = (tid & 3) * 4;
    float4 stK[4], stV[4];
#pragma unroll
    for (int i = 0; i < 4; i++) {
        stK[i] = *(const float4*)(Kg + (size_t)krow * rs + kcb + i * 16);
        stV[i] = *(const float4*)(Vg + (size_t)krow * rs + kcb + i * 16);
    }

    float m0 = -INFINITY, m1 = -INFINITY, l0a = 0.0f, l1a = 0.0f;
    float o[8][4];
#pragma unroll
    for (int nb = 0; nb < 8; nb++)
#pragma unroll
        for (int q = 0; q < 4; q++) o[nb][q] = 0.0f;

    for (int jt = 0; jt < SEQ / 64; jt++) {
        __syncthreads();   // prev-tile smem reads done (also covers Q store, iter 0)

        // store staged K (row-major, split) and V (transposed, split)
#pragma unroll
        for (int i = 0; i < 4; i++) {
            const int cf = kcb + i * 16;
            uint32_t h0, h1, l0, l1;
            split2(stK[i].x, stK[i].y, h0, l0);
            split2(stK[i].z, stK[i].w, h1, l1);
            uint32_t off = (uint32_t)(krow * ASROW + cf * 2);
            *(uint2*)(smc + AKHI + off) = make_uint2(h0, h1);
            *(uint2*)(smc + AKLO + off) = make_uint2(l0, l1);
            const float vv[4] = {stV[i].x, stV[i].y, stV[i].z, stV[i].w};
#pragma unroll
            for (int e = 0; e < 4; e++) {
                const int hd = cf + e;
                __nv_bfloat16 vh = __float2bfloat16(vv[e]);
                __nv_bfloat16 vl = __float2bfloat16(vv[e] - __bfloat162float(vh));
                *(__nv_bfloat16*)(smc + AVHI + hd * ASROW + krow * 2) = vh;
                *(__nv_bfloat16*)(smc + AVLO + hd * ASROW + krow * 2) = vl;
            }
        }
        __syncthreads();

        // prefetch next tile
        if (jt + 1 < SEQ / 64) {
            const size_t ro = (size_t)((jt + 1) * 64 + krow) * rs;
#pragma unroll
            for (int i = 0; i < 4; i++) {
                stK[i] = *(const float4*)(Kg + ro + kcb + i * 16);
                stV[i] = *(const float4*)(Vg + ro + kcb + i * 16);
            }
        }

        // ---- S = Q K^T (pre-scaled), 3-term split ----
        float s[8][4];
#pragma unroll
        for (int nb = 0; nb < 8; nb++)
#pragma unroll
            for (int q = 0; q < 4; q++) s[nb][q] = 0.0f;

        const uint32_t qbase = sb + AQHI + (uint32_t)(wid * 16 * ASROW) + a_lm;
#pragma unroll
        for (int ks = 0; ks < 4; ks++) {
            uint32_t qh[4], ql[4];
            ldm_x4(qh[0], qh[1], qh[2], qh[3], qbase + ks * 32);
            ldm_x4(ql[0], ql[1], ql[2], ql[3],
                   qbase + (AQLO - AQHI) + ks * 32);
#pragma unroll
            for (int nb2 = 0; nb2 < 4; nb2++) {
                const uint32_t kb = sb + AKHI + (uint32_t)(nb2 * 16 * ASROW)
                                  + b_lm + ks * 32;
                uint32_t h0, h1, h2, h3, L0, L1, L2, L3;
                ldm_x4(h0, h1, h2, h3, kb);
                ldm_x4(L0, L1, L2, L3, kb + (AKLO - AKHI));
                uint32_t bh0[2] = {h0, h1}, bh1[2] = {h2, h3};
                uint32_t bl0[2] = {L0, L1}, bl1[2] = {L2, L3};
                mma_bf16(s[2 * nb2],     qh, bh0);
                mma_bf16(s[2 * nb2],     qh, bl0);
                mma_bf16(s[2 * nb2],     ql, bh0);
                mma_bf16(s[2 * nb2 + 1], qh, bh1);
                mma_bf16(s[2 * nb2 + 1], qh, bl1);
                mma_bf16(s[2 * nb2 + 1], ql, bh1);
            }
        }

        // ---- online softmax (rows g and g+8; quad shfl) ----
        float mx0 = -INFINITY, mx1 = -INFINITY;
#pragma unroll
        for (int nb = 0; nb < 8; nb++) {
            mx0 = fmaxf(mx0, fmaxf(s[nb][0], s[nb][1]));
            mx1 = fmaxf(mx1, fmaxf(s[nb][2], s[nb][3]));
        }
        mx0 = fmaxf(mx0, __shfl_xor_sync(0xffffffffu, mx0, 1));
        mx0 = fmaxf(mx0, __shfl_xor_sync(0xffffffffu, mx0, 2));
        mx1 = fmaxf(mx1, __shfl_xor_sync(0xffffffffu, mx1, 1));
        mx1 = fmaxf(mx1, __shfl_xor_sync(0xffffffffu, mx1, 2));

        const float mn0 = fmaxf(m0, mx0);
        const float mn1 = fmaxf(m1, mx1);
        const float al0 = __expf(m0 - mn0);
        const float al1 = __expf(m1 - mn1);
        m0 = mn0; m1 = mn1;

        float rs0 = 0.0f, rs1 = 0.0f;
#pragma unroll
        for (int nb = 0; nb < 8; nb++) {
            s[nb][0] = __expf(s[nb][0] - m0);
            s[nb][1] = __expf(s[nb][1] - m0);
            s[nb][2] = __expf(s[nb][2] - m1);
            s[nb][3] = __expf(s[nb][3] - m1);
            rs0 += s[nb][0] + s[nb][1];
            rs1 += s[nb][2] + s[nb][3];
        }
        rs0 += __shfl_xor_sync(0xffffffffu, rs0, 1);
        rs0 += __shfl_xor_sync(0xffffffffu, rs0, 2);
        rs1 += __shfl_xor_sync(0xffffffffu, rs1, 1);
        rs1 += __shfl_xor_sync(0xffffffffu, rs1, 2);
        l0a = l0a * al0 + rs0;
        l1a = l1a * al1 + rs1;

#pragma unroll
        for (int nb = 0; nb < 8; nb++) {
            o[nb][0] *= al0; o[nb][1] *= al0;
            o[nb][2] *= al1; o[nb][3] *= al1;
        }

        // ---- O += P V (P from regs, split; V from smem) ----
#pragma unroll
        for (int ks2 = 0; ks2 < 4; ks2++) {
            uint32_t ph[4], pl[4];
            split2(s[2 * ks2][0],     s[2 * ks2][1],     ph[0], pl[0]);
            split2(s[2 * ks2][2],     s[2 * ks2][3],     ph[1], pl[1]);
            split2(s[2 * ks2 + 1][0], s[2 * ks2 + 1][1], ph[2], pl[2]);
            split2(s[2 * ks2 + 1][2], s[2 * ks2 + 1][3], ph[3], pl[3]);
#pragma unroll
            for (int nb2 = 0; nb2 < 4; nb2++) {
                const uint32_t vb = sb + AVHI + (uint32_t)(nb2 * 16 * ASROW)
                                  + b_lm + ks2 * 32;
                uint32_t h0, h1, h2, h3, L0, L1, L2, L3;
                ldm_x4(h0, h1, h2, h3, vb);
                ldm_x4(L0, L1, L2, L3, vb + (AVLO - AVHI));
                uint32_t vh0[2] = {h0, h1}, vh1[2] = {h2, h3};
                uint32_t vl0[2] = {L0, L1}, vl1[2] = {L2, L3};
                mma_bf16(o[2 * nb2],     ph, vh0);
                mma_bf16(o[2 * nb2],     ph, vl0);
                mma_bf16(o[2 * nb2],     pl, vh0);
                mma_bf16(o[2 * nb2 + 1], ph, vh1);
                mma_bf16(o[2 * nb2 + 1], ph, vl1);
                mma_bf16(o[2 * nb2 + 1], pl, vh1);
            }
        }
    }

    // ---- epilogue ----
    const float inv0 = 1.0f / l0a;
    const float inv1 = 1.0f / l1a;
    const int g = lane >> 2;
    const size_t tok0 = (size_t)b * SEQ + qt * 128 + wid * 16 + g;
#pragma unroll
    for (int nb = 0; nb < 8; nb++) {
        const int col = h * HDIM + nb * 8 + (lane & 3) * 2;
        *(float2*)(ao + tok0 * DIM + col) =
            make_float2(o[nb][0] * inv0, o[nb][1] * inv0);
        *(float2*)(ao + (tok0 + 8) * DIM + col) =
            make_float2(o[nb][2] * inv1, o[nb][3] * inv1);
    }
}

// ===========================================================================
extern "C" void kernel_launch(void* const* d_in, const int* in_sizes, int n_in,
                              void* d_out, int out_size)
{
    const float* x      = (const float*)d_in[0];
    const float* w_qkv  = (const float*)d_in[1];
    const float* w_proj = (const float*)d_in[2];
    const float* b_proj = (const float*)d_in[3];
    float* out = (float*)d_out;

    float* qkv = nullptr;
    float* ao  = nullptr;
    cudaGetSymbolAddress((void**)&qkv, g_qkv);
    cudaGetSymbolAddress((void**)&ao,  g_ao);

    cudaFuncSetAttribute(gemm_mma_kernel,
                         cudaFuncAttributeMaxDynamicSharedMemorySize, SMEM_GEMM);
    cudaFuncSetAttribute(attn_mma_kernel,
                         cudaFuncAttributeMaxDynamicSharedMemorySize, ASMEM);

    // 1) QKV projection
    dim3 g1(QKV_E / 128, M_TOK / 128);
    gemm_mma_kernel<<<g1, 256, SMEM_GEMM>>>(x, w_qkv, nullptr, qkv, QKV_E, DIM);

    // 2) Attention (HMMA flash)
    dim3 g2(SEQ / 128, BATCH * NHEAD);   // (8, 192)
    attn_mma_kernel<<<g2, 256, ASMEM>>>(qkv, ao);

    // 3) Output projection
    dim3 g3(DIM / 128, M_TOK / 128);
    gemm_mma_kernel<<<g3, 256, SMEM_GEMM>>>(ao, w_proj, b_proj, out, DIM, DIM);
}